// round 3
// baseline (speedup 1.0000x reference)
#include <cuda_runtime.h>
#include <cuda_bf16.h>

// FeedForwardQuantum: out = relu(cos(x+theta) @ W1 + b1) @ W2 + b2
// B=64, S=8192, E=8, F=32  -> 524288 rows of tiny GEMMs.
// Strategy: per-thread row compute with packed fp32x2 FMAs (fma.rn.f32x2),
// output columns paired into the two f32 lanes so shared-memory weight pairs
// load directly as 8B; 2 rows per thread amortize every weight load over two
// FFMA2s. Weights/biases/theta staged in shared memory once per CTA.

#define E_DIM 8
#define F_DIM 32
#define N_ROWS (64 * 8192)          // 524288
#define TPB 256
#define ROWS_PER_BLOCK (TPB * 2)    // R = 2 rows per thread
#define NBLOCKS (N_ROWS / ROWS_PER_BLOCK)  // 1024

__device__ __forceinline__ unsigned long long pack2(float lo, float hi) {
    unsigned long long r;
    asm("mov.b64 %0, {%1, %2};" : "=l"(r) : "f"(lo), "f"(hi));
    return r;
}

__device__ __forceinline__ void unpack2(unsigned long long v, float &lo, float &hi) {
    asm("mov.b64 {%0, %1}, %2;" : "=f"(lo), "=f"(hi) : "l"(v));
}

__device__ __forceinline__ void ffma2(unsigned long long &d,
                                      unsigned long long a,
                                      unsigned long long b) {
    asm("fma.rn.f32x2 %0, %1, %2, %3;" : "=l"(d) : "l"(a), "l"(b), "l"(d));
}

__global__ __launch_bounds__(TPB, 1)
void ffq_kernel(const float* __restrict__ x,
                const float* __restrict__ theta,
                const float* __restrict__ w1,
                const float* __restrict__ b1,
                const float* __restrict__ w2,
                const float* __restrict__ b2,
                float* __restrict__ out) {
    // Shared staging: weights as pre-paired float2 so LDS.64 feeds FFMA2 directly.
    __shared__ float2 sw1[E_DIM][F_DIM / 2];   // (w1[i][2j], w1[i][2j+1])
    __shared__ float2 sb1[F_DIM / 2];
    __shared__ float2 sw2[F_DIM][E_DIM / 2];   // (w2[k][2j], w2[k][2j+1])
    __shared__ float2 sb2[E_DIM / 2];
    __shared__ float  sth[E_DIM];

    const int tid = threadIdx.x;

    if (tid < 128) {                                // 8*16 = 128 w1 pairs
        int i = tid >> 4, j = tid & 15;
        sw1[i][j] = make_float2(w1[i * F_DIM + 2 * j], w1[i * F_DIM + 2 * j + 1]);
    } else {                                        // 32*4 = 128 w2 pairs
        int t = tid - 128;
        int k = t >> 2, j = t & 3;
        sw2[k][j] = make_float2(w2[k * E_DIM + 2 * j], w2[k * E_DIM + 2 * j + 1]);
    }
    if (tid < 16)                  sb1[tid]      = make_float2(b1[2 * tid], b1[2 * tid + 1]);
    else if (tid < 20)             sb2[tid - 16] = make_float2(b2[2 * (tid - 16)], b2[2 * (tid - 16) + 1]);
    else if (tid < 28)             sth[tid - 20] = theta[tid - 20];
    __syncthreads();

    const int r0 = blockIdx.x * ROWS_PER_BLOCK + tid;   // row 0 for this thread
    const int r1 = r0 + TPB;                            // row 1 (coalesced)

    // ---- Load x rows (2x 16B per row, coalesced 1KB/warp segments) ----
    const float4 a0 = *reinterpret_cast<const float4*>(x + (size_t)r0 * E_DIM);
    const float4 a1 = *reinterpret_cast<const float4*>(x + (size_t)r0 * E_DIM + 4);
    const float4 c0 = *reinterpret_cast<const float4*>(x + (size_t)r1 * E_DIM);
    const float4 c1 = *reinterpret_cast<const float4*>(x + (size_t)r1 * E_DIM + 4);

    float xv0[E_DIM] = {a0.x, a0.y, a0.z, a0.w, a1.x, a1.y, a1.z, a1.w};
    float xv1[E_DIM] = {c0.x, c0.y, c0.z, c0.w, c1.x, c1.y, c1.z, c1.w};

    // ---- q = cos(x + theta), pre-packed as (q, q) broadcast pairs ----
    unsigned long long qd0[E_DIM], qd1[E_DIM];
    #pragma unroll
    for (int i = 0; i < E_DIM; i++) {
        float th = sth[i];
        float q0 = __cosf(xv0[i] + th);
        float q1 = __cosf(xv1[i] + th);
        qd0[i] = pack2(q0, q0);
        qd1[i] = pack2(q1, q1);
    }

    // ---- GEMM1: h[32] = q @ W1 + b1, columns paired in f32x2 lanes ----
    unsigned long long h0[F_DIM / 2], h1[F_DIM / 2];
    #pragma unroll
    for (int j = 0; j < F_DIM / 2; j++) {
        unsigned long long b = *reinterpret_cast<const unsigned long long*>(&sb1[j]);
        h0[j] = b;
        h1[j] = b;
    }
    #pragma unroll
    for (int i = 0; i < E_DIM; i++) {
        #pragma unroll
        for (int j = 0; j < F_DIM / 2; j++) {
            unsigned long long w = *reinterpret_cast<const unsigned long long*>(&sw1[i][j]);
            ffma2(h0[j], qd0[i], w);   // one weight load feeds both rows
            ffma2(h1[j], qd1[i], w);
        }
    }

    // ---- ReLU (unpack to scalars; needed as broadcasts for GEMM2) ----
    float hs0[F_DIM], hs1[F_DIM];
    #pragma unroll
    for (int j = 0; j < F_DIM / 2; j++) {
        float lo, hi;
        unpack2(h0[j], lo, hi);
        hs0[2 * j]     = fmaxf(lo, 0.0f);
        hs0[2 * j + 1] = fmaxf(hi, 0.0f);
        unpack2(h1[j], lo, hi);
        hs1[2 * j]     = fmaxf(lo, 0.0f);
        hs1[2 * j + 1] = fmaxf(hi, 0.0f);
    }

    // ---- GEMM2: out[8] = h @ W2 + b2, output columns paired ----
    unsigned long long o0[E_DIM / 2], o1[E_DIM / 2];
    #pragma unroll
    for (int j = 0; j < E_DIM / 2; j++) {
        unsigned long long b = *reinterpret_cast<const unsigned long long*>(&sb2[j]);
        o0[j] = b;
        o1[j] = b;
    }
    #pragma unroll
    for (int k = 0; k < F_DIM; k++) {
        unsigned long long hd0 = pack2(hs0[k], hs0[k]);
        unsigned long long hd1 = pack2(hs1[k], hs1[k]);
        #pragma unroll
        for (int j = 0; j < E_DIM / 2; j++) {
            unsigned long long w = *reinterpret_cast<const unsigned long long*>(&sw2[k][j]);
            ffma2(o0[j], hd0, w);
            ffma2(o1[j], hd1, w);
        }
    }

    // ---- Store: 2x 16B per row ----
    float r0v[E_DIM], r1v[E_DIM];
    #pragma unroll
    for (int j = 0; j < E_DIM / 2; j++) {
        unpack2(o0[j], r0v[2 * j], r0v[2 * j + 1]);
        unpack2(o1[j], r1v[2 * j], r1v[2 * j + 1]);
    }
    *reinterpret_cast<float4*>(out + (size_t)r0 * E_DIM)     = make_float4(r0v[0], r0v[1], r0v[2], r0v[3]);
    *reinterpret_cast<float4*>(out + (size_t)r0 * E_DIM + 4) = make_float4(r0v[4], r0v[5], r0v[6], r0v[7]);
    *reinterpret_cast<float4*>(out + (size_t)r1 * E_DIM)     = make_float4(r1v[0], r1v[1], r1v[2], r1v[3]);
    *reinterpret_cast<float4*>(out + (size_t)r1 * E_DIM + 4) = make_float4(r1v[4], r1v[5], r1v[6], r1v[7]);
}

extern "C" void kernel_launch(void* const* d_in, const int* in_sizes, int n_in,
                              void* d_out, int out_size) {
    const float* x     = (const float*)d_in[0];   // [64, 8192, 8]
    const float* theta = (const float*)d_in[1];   // [8]
    const float* w1    = (const float*)d_in[2];   // [8, 32]
    const float* b1    = (const float*)d_in[3];   // [32]
    const float* w2    = (const float*)d_in[4];   // [32, 8]
    const float* b2    = (const float*)d_in[5];   // [8]
    float* out = (float*)d_out;                   // [64, 8192, 8]

    ffq_kernel<<<NBLOCKS, TPB>>>(x, theta, w1, b1, w2, b2, out);
}